// round 9
// baseline (speedup 1.0000x reference)
#include <cuda_runtime.h>
#include <cuda_fp16.h>
#include <math.h>

#define B_  4
#define C_  2
#define H_  2048
#define W_  128
#define HP  2050
#define WP  130

typedef unsigned long long u64;

__device__ __forceinline__ u64 ffma2(u64 a, u64 b, u64 c) {
    u64 d; asm("fma.rn.f32x2 %0, %1, %2, %3;" : "=l"(d) : "l"(a), "l"(b), "l"(c)); return d;
}
__device__ __forceinline__ u64 dup2(float x) {
    u64 d; asm("mov.b64 %0, {%1, %1};" : "=l"(d) : "f"(x)); return d;
}
__device__ __forceinline__ u64 pk2(float x, float y) {
    u64 d; asm("mov.b64 %0, {%1, %2};" : "=l"(d) : "f"(x), "f"(y)); return d;
}
__device__ __forceinline__ float2 un2(u64 v) {
    float2 r; asm("mov.b64 {%0, %1}, %2;" : "=f"(r.x), "=f"(r.y) : "l"(v)); return r;
}
__device__ __forceinline__ __half2 h2dup(float x) {
    unsigned r; asm("cvt.rn.f16x2.f32 %0, %1, %1;" : "=r"(r) : "f"(x));
    return *(__half2*)&r;
}

// Scratch
__device__ float      g_fm[B_ * C_ * 128 * 128];  // fm after sigmoid [b][c][k][w]
__device__ float4     g_xp4[B_ * HP * WP];        // padded NHWC fp32 (sar0,sar1,fs0,fs1)
__device__ ulonglong2 g_xh2[B_ * HP * WP];        // x-duplicated fp16: slot x = (px[x], px[x+1])

// ---------------------------------------------------------------------------
// Kernel AZ: fused (avg+fm, split reduction) and border-zero
// blocks [0,512): kA; blocks [512,545): border zero
// ---------------------------------------------------------------------------
__global__ void kAZ(const float* __restrict__ rgb, const float* __restrict__ wfm) {
    if (blockIdx.x < 512) {
        __shared__ float red[128][2];
        int b = blockIdx.x >> 7;
        int i = blockIdx.x & 127;
        int j = threadIdx.x & 127;
        int half = threadIdx.x >> 7;

        const float* r0 = rgb + ((size_t)(b * 2 + 0) * H_ + i * 16 + half * 8) * W_ + j;
        const float* r1 = rgb + ((size_t)(b * 2 + 1) * H_ + i * 16 + half * 8) * W_ + j;
        float a0 = 0.f, a1 = 0.f;
#pragma unroll
        for (int r = 0; r < 8; r++) {
            a0 += __ldg(&r0[r * W_]);
            a1 += __ldg(&r1[r * W_]);
        }
        if (half == 1) { red[j][0] = a0; red[j][1] = a1; }
        __syncthreads();
        if (half == 0) {
            a0 = (a0 + red[j][0]) * (1.f / 16.f);
            a1 = (a1 + red[j][1]) * (1.f / 16.f);
            float w00 = __ldg(&wfm[0]), w01 = __ldg(&wfm[1]);
            float w10 = __ldg(&wfm[2]), w11 = __ldg(&wfm[3]);
            float z0 = w00 * a0 + w01 * a1;
            float z1 = w10 * a0 + w11 * a1;
            g_fm[((b * 2 + 0) * 128 + i) * 128 + j] = 1.f / (1.f + expf(-z0));
            g_fm[((b * 2 + 1) * 128 + i) * 128 + j] = 1.f / (1.f + expf(-z1));
        }
    } else {
        int tid = (blockIdx.x - 512) * 256 + threadIdx.x;
        if (tid >= B_ * HP) return;
        int b = tid / HP;
        int y = tid % HP;
        size_t rb = ((size_t)b * HP + y) * WP;
        float4 z4 = make_float4(0.f, 0.f, 0.f, 0.f);
        u64* s = (u64*)(g_xh2 + rb);
        if (y == 0 || y == HP - 1) {
            for (int x = 0; x < WP; x++) {
                g_xp4[rb + x] = z4;
                s[x * 2] = 0ULL; s[x * 2 + 1] = 0ULL;
            }
        } else {
            g_xp4[rb] = z4;
            g_xp4[rb + WP - 1] = z4;
            s[0] = 0ULL;
            s[(WP - 2) * 2 + 1] = 0ULL;
            s[(WP - 1) * 2] = 0ULL;
            s[(WP - 1) * 2 + 1] = 0ULL;
        }
    }
}

// ---------------------------------------------------------------------------
// Kernel B: mat = rgb @ fm + rgb, fs mix, pack fp32 NHWC + fp16 dup buffer.
// 512 threads (16 warps/SM), thread tile 4 rows x 4 cols, tile 64x128.
// ---------------------------------------------------------------------------
#define KB_ROWS 64
__global__ void __launch_bounds__(512, 1)
kB_mat_fs_pack(const float* __restrict__ rgb,
               const float* __restrict__ sar,
               const float* __restrict__ wfs) {
    extern __shared__ float sm[];
    float* s_fmi  = sm;            // [k][w][ch]   32768 floats
    float* s_rgbi = sm + 32768;    // [r][k][ch]   16384 floats

    int t = threadIdx.x;
    int lane = t & 31;
    int warp = t >> 5;             // 0..15
    int c0 = lane * 4;
    int r0 = warp * 4;
    int b  = blockIdx.y;
    int h0 = blockIdx.x * KB_ROWS;

    // vectorized interleaved fills
    const float* fmb = g_fm + (size_t)b * 32768;
#pragma unroll
    for (int i = t; i < 8192; i += 512) {
        int idx = i * 2;  // even element index in [k][w] space
        float2 f0 = *(const float2*)&fmb[idx];
        float2 f1 = *(const float2*)&fmb[16384 + idx];
        *(float4*)&s_fmi[idx * 2] = make_float4(f0.x, f1.x, f0.y, f1.y);
    }
    const float* rgbb = rgb + (size_t)b * 2 * H_ * W_;
#pragma unroll
    for (int i = t; i < 4096; i += 512) {
        int idx = i * 2;
        int r = idx >> 7, k = idx & 127;
        float2 f0 = *(const float2*)&rgbb[(size_t)(h0 + r) * W_ + k];
        float2 f1 = *(const float2*)&rgbb[(size_t)H_ * W_ + (size_t)(h0 + r) * W_ + k];
        *(float4*)&s_rgbi[idx * 2] = make_float4(f0.x, f1.x, f0.y, f1.y);
    }
    __syncthreads();

    u64 acc[4][4];
#pragma unroll
    for (int r = 0; r < 4; r++)
#pragma unroll
        for (int c = 0; c < 4; c++) acc[r][c] = 0ULL;

#pragma unroll 4
    for (int k = 0; k < 128; k++) {
        const ulonglong2* fp = (const ulonglong2*)&s_fmi[(k * 128 + c0) * 2];
        ulonglong2 fA = fp[0], fB = fp[1];
#pragma unroll
        for (int r = 0; r < 4; r++) {
            u64 xv = *(const u64*)&s_rgbi[((r0 + r) * 128 + k) * 2];  // broadcast
            acc[r][0] = ffma2(xv, fA.x, acc[r][0]);
            acc[r][1] = ffma2(xv, fA.y, acc[r][1]);
            acc[r][2] = ffma2(xv, fB.x, acc[r][2]);
            acc[r][3] = ffma2(xv, fB.y, acc[r][3]);
        }
    }

    float wfs00 = __ldg(&wfs[0]), wfs01 = __ldg(&wfs[1]);
    float wfs10 = __ldg(&wfs[2]), wfs11 = __ldg(&wfs[3]);
    const float* sarb = sar + (size_t)b * 2 * H_ * W_;
    float4* xb = g_xp4 + (size_t)b * HP * WP;
    u64*    hb = (u64*)(g_xh2 + (size_t)b * HP * WP);

#pragma unroll
    for (int r = 0; r < 4; r++) {
        int row = r0 + r;
        int h = h0 + row;
        float4 sA = *(const float4*)&sarb[(size_t)h * W_ + c0];
        float4 sB = *(const float4*)&sarb[(size_t)H_ * W_ + (size_t)h * W_ + c0];
        float sc0[4] = {sA.x, sA.y, sA.z, sA.w};
        float sc1[4] = {sB.x, sB.y, sB.z, sB.w};
#pragma unroll
        for (int c = 0; c < 4; c++) {
            float2 m = un2(acc[r][c]);
            float2 xf = un2(*(const u64*)&s_rgbi[(row * 128 + c0 + c) * 2]);
            float mat0 = m.x + xf.x;
            float mat1 = m.y + xf.y;
            float fs0 = wfs00 * mat0 + wfs01 * mat1;
            float fs1 = wfs10 * mat0 + wfs11 * mat1;
            int p = c0 + c + 1;
            size_t ridx = (size_t)(h + 1) * WP;
            xb[ridx + p] = make_float4(sc0[c], sc1[c], fs0, fs1);
            __half2 ha = __floats2half2_rn(sc0[c], sc1[c]);
            __half2 hh = __floats2half2_rn(fs0, fs1);
            u64 hv = ((u64)(*(unsigned*)&hh) << 32) | (u64)(*(unsigned*)&ha);
            hb[(ridx + p) * 2] = hv;
            hb[(ridx + p - 1) * 2 + 1] = hv;
        }
    }
}

// ---------------------------------------------------------------------------
// Kernel C: software-pipelined offset conv + deform sampling.
// fp16 x-interp combine (HMUL2/HFMA2). Unchanged from round 7/8.
// ---------------------------------------------------------------------------
__device__ __forceinline__ void comp_off(const ulonglong2 ip[4][3],
                                         const float* __restrict__ swq,
                                         const float* __restrict__ sbp, int n,
                                         float& offy0, float& offy1,
                                         float& offx0, float& offx1) {
    u64 ay0 = 0ULL, ay1 = 0ULL, ax0 = 0ULL, ax1 = 0ULL;
#pragma unroll
    for (int ky = 0; ky < 3; ky++) {
#pragma unroll
        for (int kx = 0; kx < 3; kx++) {
            int tap = ky * 3 + kx;
            ulonglong2 wy = *(const ulonglong2*)&swq[(n * 9 + tap) * 4];
            ulonglong2 wx = *(const ulonglong2*)&swq[((9 + n) * 9 + tap) * 4];
            ay0 = ffma2(ip[ky    ][kx].x, wy.x, ay0);
            ay0 = ffma2(ip[ky    ][kx].y, wy.y, ay0);
            ay1 = ffma2(ip[ky + 1][kx].x, wy.x, ay1);
            ay1 = ffma2(ip[ky + 1][kx].y, wy.y, ay1);
            ax0 = ffma2(ip[ky    ][kx].x, wx.x, ax0);
            ax0 = ffma2(ip[ky    ][kx].y, wx.y, ax0);
            ax1 = ffma2(ip[ky + 1][kx].x, wx.x, ax1);
            ax1 = ffma2(ip[ky + 1][kx].y, wx.y, ax1);
        }
    }
    float2 t;
    t = un2(ay0); offy0 = t.x + t.y + sbp[n];
    t = un2(ay1); offy1 = t.x + t.y + sbp[n];
    t = un2(ax0); offx0 = t.x + t.y + sbp[9 + n];
    t = un2(ax1); offx1 = t.x + t.y + sbp[9 + n];
}

__device__ __forceinline__ void issue_pt(const ulonglong2* __restrict__ xh2,
                                         float py, float px,
                                         ulonglong2& U0, ulonglong2& U1,
                                         float& gy, float& gx, bool& sel) {
    float fy = floorf(py), fx = floorf(px);
    gy = py - fy; gx = px - fx;   // exact: clamped corners read zero pad pixels
    int y0 = (int)fminf(fmaxf(fy,       0.f), (float)(HP - 1));
    int y1 = (int)fminf(fmaxf(fy + 1.f, 0.f), (float)(HP - 1));
    int x0 = (int)fminf(fmaxf(fx,       0.f), (float)(WP - 1));
    int x1 = (int)fminf(fmaxf(fx + 1.f, 0.f), (float)(WP - 1));
    sel = (x1 != x0);
    U0 = __ldg(&xh2[y0 * WP + x0]);
    U1 = __ldg(&xh2[y1 * WP + x0]);
}

__device__ __forceinline__ u64 combine_pt(ulonglong2 U0, ulonglong2 U1,
                                          float gy, float gx, bool sel,
                                          u64 sd0, u64 sd1, u64 sd2, u64 sd3, u64 acc) {
    unsigned p00l = (unsigned)U0.x, p00h = (unsigned)(U0.x >> 32);
    unsigned q01l = (unsigned)U0.y, q01h = (unsigned)(U0.y >> 32);
    unsigned p10l = (unsigned)U1.x, p10h = (unsigned)(U1.x >> 32);
    unsigned q11l = (unsigned)U1.y, q11h = (unsigned)(U1.y >> 32);
    unsigned p01l = sel ? q01l : p00l, p01h = sel ? q01h : p00h;
    unsigned p11l = sel ? q11l : p10l, p11h = sel ? q11h : p10h;

    __half2 hgx = h2dup(gx), hhx = h2dup(1.f - gx);

    __half2 cy0l = __hfma2(hgx, *(__half2*)&p01l, __hmul2(hhx, *(__half2*)&p00l));
    __half2 cy0h = __hfma2(hgx, *(__half2*)&p01h, __hmul2(hhx, *(__half2*)&p00h));
    __half2 cy1l = __hfma2(hgx, *(__half2*)&p11l, __hmul2(hhx, *(__half2*)&p10l));
    __half2 cy1h = __hfma2(hgx, *(__half2*)&p11h, __hmul2(hhx, *(__half2*)&p10h));

    float2 f0l = __half22float2(cy0l), f0h = __half22float2(cy0h);
    float2 f1l = __half22float2(cy1l), f1h = __half22float2(cy1h);

    u64 wy1d = dup2(gy), wy0d = dup2(1.f - gy);
    u64 c01 = ffma2(wy1d, pk2(f1l.x, f1l.y), ffma2(wy0d, pk2(f0l.x, f0l.y), 0ULL));
    u64 c23 = ffma2(wy1d, pk2(f1h.x, f1h.y), ffma2(wy0d, pk2(f0h.x, f0h.y), 0ULL));

    float2 v01 = un2(c01), v23 = un2(c23);
    acc = ffma2(dup2(v01.x), sd0, acc);
    acc = ffma2(dup2(v01.y), sd1, acc);
    acc = ffma2(dup2(v23.x), sd2, acc);
    acc = ffma2(dup2(v23.y), sd3, acc);
    return acc;
}

#define TILE_H 8
__global__ void __launch_bounds__(128, 4)
kC_deform(const float* __restrict__ wp,
          const float* __restrict__ bp,
          const float* __restrict__ wdc,
          float* __restrict__ out) {
    __shared__ __align__(16) float4 srow[TILE_H + 2][WP];
    __shared__ __align__(16) float  swq[648];   // [j][tap][c]
    __shared__ __align__(16) float  sdc[72];    // [n][c][(o0,o1)]
    __shared__ float  sbp[18];

    int w  = threadIdx.x;
    int h0 = blockIdx.x * TILE_H;
    int b  = blockIdx.y;

    const float4* base = g_xp4 + (size_t)b * HP * WP;
    const ulonglong2* xh2 = g_xh2 + (size_t)b * HP * WP;

    for (int i = threadIdx.x; i < (TILE_H + 2) * WP; i += 128) {
        int ry = i / WP, rx = i % WP;
        srow[ry][rx] = base[(size_t)(h0 + ry) * WP + rx];
    }
    for (int i = threadIdx.x; i < 648; i += 128) {
        int j = i / 36, rem = i % 36, tap = rem / 4, c = rem % 4;
        swq[i] = wp[j * 36 + c * 9 + tap];
    }
    if (threadIdx.x < 72) {
        int i = threadIdx.x;
        int n = i / 8, rc = i % 8, c = rc / 2, o = rc % 2;
        sdc[i] = wdc[o * 36 + c * 9 + n];
    }
    if (threadIdx.x < 18) sbp[threadIdx.x] = bp[threadIdx.x];
    __syncthreads();

    const float pxbase = (float)(w + 1);

#pragma unroll 1
    for (int rp = 0; rp < TILE_H / 2; rp++) {
        int r0 = rp * 2;
        ulonglong2 ip[4][3];
#pragma unroll
        for (int ry = 0; ry < 4; ry++)
#pragma unroll
            for (int kx = 0; kx < 3; kx++)
                ip[ry][kx] = *(const ulonglong2*)&srow[r0 + ry][w + kx];

        u64 accp0 = 0ULL, accp1 = 0ULL;
        float py0 = (float)(h0 + r0 + 1);
        float py1 = (float)(h0 + r0 + 2);

        ulonglong2 A0, A1, B0, B1;
        float gya, gxa, gyb, gxb;
        bool sela, selb;
        {
            float oy0, oy1, ox0, ox1;
            comp_off(ip, swq, sbp, 0, oy0, oy1, ox0, ox1);
            issue_pt(xh2, py0 - 1.f + oy0, pxbase - 1.f + ox0, A0, A1, gya, gxa, sela);
            issue_pt(xh2, py1 - 1.f + oy1, pxbase - 1.f + ox1, B0, B1, gyb, gxb, selb);
        }

#pragma unroll
        for (int n = 0; n < 9; n++) {
            ulonglong2 nA0, nA1, nB0, nB1;
            float ngya, ngxa, ngyb, ngxb;
            bool nsela = false, nselb = false;
            if (n < 8) {
                float oy0, oy1, ox0, ox1;
                comp_off(ip, swq, sbp, n + 1, oy0, oy1, ox0, ox1);
                float dy = (float)((n + 1) / 3 - 1);
                float dx = (float)((n + 1) % 3 - 1);
                issue_pt(xh2, py0 + dy + oy0, pxbase + dx + ox0, nA0, nA1, ngya, ngxa, nsela);
                issue_pt(xh2, py1 + dy + oy1, pxbase + dx + ox1, nB0, nB1, ngyb, ngxb, nselb);
            }
            const u64* sd = (const u64*)&sdc[n * 8];
            u64 sd0 = sd[0], sd1 = sd[1], sd2 = sd[2], sd3 = sd[3];
            accp0 = combine_pt(A0, A1, gya, gxa, sela, sd0, sd1, sd2, sd3, accp0);
            accp1 = combine_pt(B0, B1, gyb, gxb, selb, sd0, sd1, sd2, sd3, accp1);
            if (n < 8) {
                A0 = nA0; A1 = nA1; B0 = nB0; B1 = nB1;
                gya = ngya; gxa = ngxa; sela = nsela;
                gyb = ngyb; gxb = ngxb; selb = nselb;
            }
        }

        int h = h0 + r0;
        float2 o0 = un2(accp0);
        float2 o1 = un2(accp1);
        out[((size_t)(b * 2 + 0) * H_ + h) * W_ + w] = o0.x;
        out[((size_t)(b * 2 + 1) * H_ + h) * W_ + w] = o0.y;
        out[((size_t)(b * 2 + 0) * H_ + h + 1) * W_ + w] = o1.x;
        out[((size_t)(b * 2 + 1) * H_ + h + 1) * W_ + w] = o1.y;
    }
}

// ---------------------------------------------------------------------------
extern "C" void kernel_launch(void* const* d_in, const int* in_sizes, int n_in,
                              void* d_out, int out_size) {
    const float* rgb = (const float*)d_in[0];
    const float* sar = (const float*)d_in[1];
    const float* wfm = (const float*)d_in[2];
    const float* wfs = (const float*)d_in[3];
    const float* wp  = (const float*)d_in[4];
    const float* bp  = (const float*)d_in[5];
    const float* wdc = (const float*)d_in[6];
    float* out = (float*)d_out;

    cudaFuncSetAttribute(kB_mat_fs_pack,
                         cudaFuncAttributeMaxDynamicSharedMemorySize, 196608);

    kAZ<<<512 + 33, 256>>>(rgb, wfm);
    kB_mat_fs_pack<<<dim3(H_ / KB_ROWS, B_), 512, 196608>>>(rgb, sar, wfs);
    kC_deform<<<dim3(H_ / TILE_H, B_), 128>>>(wp, bp, wdc, out);
}

// round 11
// speedup vs baseline: 1.0064x; 1.0064x over previous
#include <cuda_runtime.h>
#include <cuda_fp16.h>
#include <math.h>

#define B_  4
#define C_  2
#define H_  2048
#define W_  128
#define HP  2050
#define WP  130

typedef unsigned long long u64;

__device__ __forceinline__ u64 ffma2(u64 a, u64 b, u64 c) {
    u64 d; asm("fma.rn.f32x2 %0, %1, %2, %3;" : "=l"(d) : "l"(a), "l"(b), "l"(c)); return d;
}
__device__ __forceinline__ u64 dup2(float x) {
    u64 d; asm("mov.b64 %0, {%1, %1};" : "=l"(d) : "f"(x)); return d;
}
__device__ __forceinline__ u64 pk2(float x, float y) {
    u64 d; asm("mov.b64 %0, {%1, %2};" : "=l"(d) : "f"(x), "f"(y)); return d;
}
__device__ __forceinline__ float2 un2(u64 v) {
    float2 r; asm("mov.b64 {%0, %1}, %2;" : "=f"(r.x), "=f"(r.y) : "l"(v)); return r;
}
__device__ __forceinline__ __half2 h2dup(float x) {
    unsigned r; asm("cvt.rn.f16x2.f32 %0, %1, %1;" : "=r"(r) : "f"(x));
    return *(__half2*)&r;
}

// Scratch
__device__ float      g_fm[B_ * C_ * 128 * 128];  // fm after sigmoid [b][c][k][w]
__device__ float4     g_xp4[B_ * HP * WP];        // padded NHWC fp32 (sar0,sar1,fs0,fs1)
__device__ ulonglong2 g_xh2[B_ * HP * WP];        // x-duplicated fp16: slot x = (px[x], px[x+1])

// ---------------------------------------------------------------------------
// Kernel AZ: fused (avg+fm with float4 loads) and border-zero
// blocks [0,512): kA; blocks [512,545): border zero
// ---------------------------------------------------------------------------
__global__ void kAZ(const float* __restrict__ rgb, const float* __restrict__ wfm) {
    if (blockIdx.x < 512) {
        __shared__ float4 red[2][4][32];
        int b = blockIdx.x >> 7;
        int i = blockIdx.x & 127;
        int t = threadIdx.x;
        int wrp = t >> 5, l = t & 31;
        int ch = wrp & 1, rg = wrp >> 1;    // channel, row-group (4 rows each)

        const float* p = rgb + ((size_t)(b * 2 + ch) * H_ + i * 16 + rg * 4) * W_ + l * 4;
        float4 s0 = *(const float4*)p;
        float4 s1 = *(const float4*)(p + W_);
        float4 s2 = *(const float4*)(p + 2 * W_);
        float4 s3 = *(const float4*)(p + 3 * W_);
        float4 s;
        s.x = s0.x + s1.x + s2.x + s3.x;
        s.y = s0.y + s1.y + s2.y + s3.y;
        s.z = s0.z + s1.z + s2.z + s3.z;
        s.w = s0.w + s1.w + s2.w + s3.w;
        red[ch][rg][l] = s;
        __syncthreads();

        if (t < 128) {
            int j = t;
            int li = j >> 2, ci = j & 3;
            float a0 = 0.f, a1 = 0.f;
#pragma unroll
            for (int g = 0; g < 4; g++) {
                a0 += ((const float*)&red[0][g][li])[ci];
                a1 += ((const float*)&red[1][g][li])[ci];
            }
            a0 *= (1.f / 16.f);
            a1 *= (1.f / 16.f);
            float w00 = __ldg(&wfm[0]), w01 = __ldg(&wfm[1]);
            float w10 = __ldg(&wfm[2]), w11 = __ldg(&wfm[3]);
            float z0 = w00 * a0 + w01 * a1;
            float z1 = w10 * a0 + w11 * a1;
            g_fm[((b * 2 + 0) * 128 + i) * 128 + j] = 1.f / (1.f + expf(-z0));
            g_fm[((b * 2 + 1) * 128 + i) * 128 + j] = 1.f / (1.f + expf(-z1));
        }
    } else {
        int tid = (blockIdx.x - 512) * 256 + threadIdx.x;
        if (tid >= B_ * HP) return;
        int b = tid / HP;
        int y = tid % HP;
        size_t rb = ((size_t)b * HP + y) * WP;
        float4 z4 = make_float4(0.f, 0.f, 0.f, 0.f);
        u64* s = (u64*)(g_xh2 + rb);
        if (y == 0 || y == HP - 1) {
            for (int x = 0; x < WP; x++) {
                g_xp4[rb + x] = z4;
                s[x * 2] = 0ULL; s[x * 2 + 1] = 0ULL;
            }
        } else {
            g_xp4[rb] = z4;
            g_xp4[rb + WP - 1] = z4;
            s[0] = 0ULL;
            s[(WP - 2) * 2 + 1] = 0ULL;
            s[(WP - 1) * 2] = 0ULL;
            s[(WP - 1) * 2 + 1] = 0ULL;
        }
    }
}

// ---------------------------------------------------------------------------
// Kernel B: mat = rgb @ fm + rgb, fs mix, pack fp32 NHWC + fp16 dup buffer.
// (round-8 measured-good version: 256 thr, thread tile 8 rows x 4 cols)
// ---------------------------------------------------------------------------
#define KB_ROWS 64
__global__ void __launch_bounds__(256, 1)
kB_mat_fs_pack(const float* __restrict__ rgb,
               const float* __restrict__ sar,
               const float* __restrict__ wfs) {
    extern __shared__ float sm[];
    float* s_fmi  = sm;            // [k][w][ch]
    float* s_rgbi = sm + 32768;    // [r][k][ch]

    int t = threadIdx.x;
    int lane = t & 31;
    int warp = t >> 5;
    int c0 = lane * 4;
    int r0 = warp * 8;
    int b  = blockIdx.y;
    int h0 = blockIdx.x * KB_ROWS;

    const float* fmb = g_fm + (size_t)b * 32768;
    for (int i = t; i < 16384; i += 256) {
        s_fmi[i * 2 + 0] = fmb[i];
        s_fmi[i * 2 + 1] = fmb[16384 + i];
    }
    const float* rgbb = rgb + (size_t)b * 2 * H_ * W_;
    for (int i = t; i < KB_ROWS * 128; i += 256) {
        int r = i >> 7, k = i & 127;
        s_rgbi[i * 2 + 0] = rgbb[(size_t)(h0 + r) * W_ + k];
        s_rgbi[i * 2 + 1] = rgbb[(size_t)H_ * W_ + (size_t)(h0 + r) * W_ + k];
    }
    __syncthreads();

    u64 acc[8][4];
#pragma unroll
    for (int r = 0; r < 8; r++)
#pragma unroll
        for (int c = 0; c < 4; c++) acc[r][c] = 0ULL;

#pragma unroll 2
    for (int k = 0; k < 128; k++) {
        const ulonglong2* fp = (const ulonglong2*)&s_fmi[(k * 128 + c0) * 2];
        ulonglong2 fA = fp[0], fB = fp[1];
#pragma unroll
        for (int r = 0; r < 8; r++) {
            u64 xv = *(const u64*)&s_rgbi[((r0 + r) * 128 + k) * 2];  // broadcast
            acc[r][0] = ffma2(xv, fA.x, acc[r][0]);
            acc[r][1] = ffma2(xv, fA.y, acc[r][1]);
            acc[r][2] = ffma2(xv, fB.x, acc[r][2]);
            acc[r][3] = ffma2(xv, fB.y, acc[r][3]);
        }
    }

    float wfs00 = __ldg(&wfs[0]), wfs01 = __ldg(&wfs[1]);
    float wfs10 = __ldg(&wfs[2]), wfs11 = __ldg(&wfs[3]);
    const float* sarb = sar + (size_t)b * 2 * H_ * W_;
    float4* xb = g_xp4 + (size_t)b * HP * WP;
    u64*    hb = (u64*)(g_xh2 + (size_t)b * HP * WP);

#pragma unroll
    for (int r = 0; r < 8; r++) {
        int row = r0 + r;
        int h = h0 + row;
        float4 sA = *(const float4*)&sarb[(size_t)h * W_ + c0];
        float4 sB = *(const float4*)&sarb[(size_t)H_ * W_ + (size_t)h * W_ + c0];
        float sc0[4] = {sA.x, sA.y, sA.z, sA.w};
        float sc1[4] = {sB.x, sB.y, sB.z, sB.w};
#pragma unroll
        for (int c = 0; c < 4; c++) {
            float2 m = un2(acc[r][c]);
            float2 xf = un2(*(const u64*)&s_rgbi[(row * 128 + c0 + c) * 2]);
            float mat0 = m.x + xf.x;
            float mat1 = m.y + xf.y;
            float fs0 = wfs00 * mat0 + wfs01 * mat1;
            float fs1 = wfs10 * mat0 + wfs11 * mat1;
            int p = c0 + c + 1;
            size_t ridx = (size_t)(h + 1) * WP;
            xb[ridx + p] = make_float4(sc0[c], sc1[c], fs0, fs1);
            __half2 ha = __floats2half2_rn(sc0[c], sc1[c]);
            __half2 hh = __floats2half2_rn(fs0, fs1);
            u64 hv = ((u64)(*(unsigned*)&hh) << 32) | (u64)(*(unsigned*)&ha);
            hb[(ridx + p) * 2] = hv;
            hb[(ridx + p - 1) * 2 + 1] = hv;
        }
    }
}

// ---------------------------------------------------------------------------
// Kernel C: software-pipelined offset conv + deform sampling (fp16 x-interp).
// lb 4 -> 5 for 20 warps/SM.
// ---------------------------------------------------------------------------
__device__ __forceinline__ void comp_off(const ulonglong2 ip[4][3],
                                         const float* __restrict__ swq,
                                         const float* __restrict__ sbp, int n,
                                         float& offy0, float& offy1,
                                         float& offx0, float& offx1) {
    u64 ay0 = 0ULL, ay1 = 0ULL, ax0 = 0ULL, ax1 = 0ULL;
#pragma unroll
    for (int ky = 0; ky < 3; ky++) {
#pragma unroll
        for (int kx = 0; kx < 3; kx++) {
            int tap = ky * 3 + kx;
            ulonglong2 wy = *(const ulonglong2*)&swq[(n * 9 + tap) * 4];
            ulonglong2 wx = *(const ulonglong2*)&swq[((9 + n) * 9 + tap) * 4];
            ay0 = ffma2(ip[ky    ][kx].x, wy.x, ay0);
            ay0 = ffma2(ip[ky    ][kx].y, wy.y, ay0);
            ay1 = ffma2(ip[ky + 1][kx].x, wy.x, ay1);
            ay1 = ffma2(ip[ky + 1][kx].y, wy.y, ay1);
            ax0 = ffma2(ip[ky    ][kx].x, wx.x, ax0);
            ax0 = ffma2(ip[ky    ][kx].y, wx.y, ax0);
            ax1 = ffma2(ip[ky + 1][kx].x, wx.x, ax1);
            ax1 = ffma2(ip[ky + 1][kx].y, wx.y, ax1);
        }
    }
    float2 t;
    t = un2(ay0); offy0 = t.x + t.y + sbp[n];
    t = un2(ay1); offy1 = t.x + t.y + sbp[n];
    t = un2(ax0); offx0 = t.x + t.y + sbp[9 + n];
    t = un2(ax1); offx1 = t.x + t.y + sbp[9 + n];
}

__device__ __forceinline__ void issue_pt(const ulonglong2* __restrict__ xh2,
                                         float py, float px,
                                         ulonglong2& U0, ulonglong2& U1,
                                         float& gy, float& gx, bool& sel) {
    float fy = floorf(py), fx = floorf(px);
    gy = py - fy; gx = px - fx;   // exact: clamped corners read zero pad pixels
    int y0 = (int)fminf(fmaxf(fy,       0.f), (float)(HP - 1));
    int y1 = (int)fminf(fmaxf(fy + 1.f, 0.f), (float)(HP - 1));
    int x0 = (int)fminf(fmaxf(fx,       0.f), (float)(WP - 1));
    int x1 = (int)fminf(fmaxf(fx + 1.f, 0.f), (float)(WP - 1));
    sel = (x1 != x0);
    U0 = __ldg(&xh2[y0 * WP + x0]);
    U1 = __ldg(&xh2[y1 * WP + x0]);
}

__device__ __forceinline__ u64 combine_pt(ulonglong2 U0, ulonglong2 U1,
                                          float gy, float gx, bool sel,
                                          u64 sd0, u64 sd1, u64 sd2, u64 sd3, u64 acc) {
    unsigned p00l = (unsigned)U0.x, p00h = (unsigned)(U0.x >> 32);
    unsigned q01l = (unsigned)U0.y, q01h = (unsigned)(U0.y >> 32);
    unsigned p10l = (unsigned)U1.x, p10h = (unsigned)(U1.x >> 32);
    unsigned q11l = (unsigned)U1.y, q11h = (unsigned)(U1.y >> 32);
    unsigned p01l = sel ? q01l : p00l, p01h = sel ? q01h : p00h;
    unsigned p11l = sel ? q11l : p10l, p11h = sel ? q11h : p10h;

    __half2 hgx = h2dup(gx), hhx = h2dup(1.f - gx);

    __half2 cy0l = __hfma2(hgx, *(__half2*)&p01l, __hmul2(hhx, *(__half2*)&p00l));
    __half2 cy0h = __hfma2(hgx, *(__half2*)&p01h, __hmul2(hhx, *(__half2*)&p00h));
    __half2 cy1l = __hfma2(hgx, *(__half2*)&p11l, __hmul2(hhx, *(__half2*)&p10l));
    __half2 cy1h = __hfma2(hgx, *(__half2*)&p11h, __hmul2(hhx, *(__half2*)&p10h));

    float2 f0l = __half22float2(cy0l), f0h = __half22float2(cy0h);
    float2 f1l = __half22float2(cy1l), f1h = __half22float2(cy1h);

    u64 wy1d = dup2(gy), wy0d = dup2(1.f - gy);
    u64 c01 = ffma2(wy1d, pk2(f1l.x, f1l.y), ffma2(wy0d, pk2(f0l.x, f0l.y), 0ULL));
    u64 c23 = ffma2(wy1d, pk2(f1h.x, f1h.y), ffma2(wy0d, pk2(f0h.x, f0h.y), 0ULL));

    float2 v01 = un2(c01), v23 = un2(c23);
    acc = ffma2(dup2(v01.x), sd0, acc);
    acc = ffma2(dup2(v01.y), sd1, acc);
    acc = ffma2(dup2(v23.x), sd2, acc);
    acc = ffma2(dup2(v23.y), sd3, acc);
    return acc;
}

#define TILE_H 8
__global__ void __launch_bounds__(128, 5)
kC_deform(const float* __restrict__ wp,
          const float* __restrict__ bp,
          const float* __restrict__ wdc,
          float* __restrict__ out) {
    __shared__ __align__(16) float4 srow[TILE_H + 2][WP];
    __shared__ __align__(16) float  swq[648];   // [j][tap][c]
    __shared__ __align__(16) float  sdc[72];    // [n][c][(o0,o1)]
    __shared__ float  sbp[18];

    int w  = threadIdx.x;
    int h0 = blockIdx.x * TILE_H;
    int b  = blockIdx.y;

    const float4* base = g_xp4 + (size_t)b * HP * WP;
    const ulonglong2* xh2 = g_xh2 + (size_t)b * HP * WP;

    for (int i = threadIdx.x; i < (TILE_H + 2) * WP; i += 128) {
        int ry = i / WP, rx = i % WP;
        srow[ry][rx] = base[(size_t)(h0 + ry) * WP + rx];
    }
    for (int i = threadIdx.x; i < 648; i += 128) {
        int j = i / 36, rem = i % 36, tap = rem / 4, c = rem % 4;
        swq[i] = wp[j * 36 + c * 9 + tap];
    }
    if (threadIdx.x < 72) {
        int i = threadIdx.x;
        int n = i / 8, rc = i % 8, c = rc / 2, o = rc % 2;
        sdc[i] = wdc[o * 36 + c * 9 + n];
    }
    if (threadIdx.x < 18) sbp[threadIdx.x] = bp[threadIdx.x];
    __syncthreads();

    const float pxbase = (float)(w + 1);

#pragma unroll 1
    for (int rp = 0; rp < TILE_H / 2; rp++) {
        int r0 = rp * 2;
        ulonglong2 ip[4][3];
#pragma unroll
        for (int ry = 0; ry < 4; ry++)
#pragma unroll
            for (int kx = 0; kx < 3; kx++)
                ip[ry][kx] = *(const ulonglong2*)&srow[r0 + ry][w + kx];

        u64 accp0 = 0ULL, accp1 = 0ULL;
        float py0 = (float)(h0 + r0 + 1);
        float py1 = (float)(h0 + r0 + 2);

        ulonglong2 A0, A1, B0, B1;
        float gya, gxa, gyb, gxb;
        bool sela, selb;
        {
            float oy0, oy1, ox0, ox1;
            comp_off(ip, swq, sbp, 0, oy0, oy1, ox0, ox1);
            issue_pt(xh2, py0 - 1.f + oy0, pxbase - 1.f + ox0, A0, A1, gya, gxa, sela);
            issue_pt(xh2, py1 - 1.f + oy1, pxbase - 1.f + ox1, B0, B1, gyb, gxb, selb);
        }

#pragma unroll
        for (int n = 0; n < 9; n++) {
            ulonglong2 nA0, nA1, nB0, nB1;
            float ngya, ngxa, ngyb, ngxb;
            bool nsela = false, nselb = false;
            if (n < 8) {
                float oy0, oy1, ox0, ox1;
                comp_off(ip, swq, sbp, n + 1, oy0, oy1, ox0, ox1);
                float dy = (float)((n + 1) / 3 - 1);
                float dx = (float)((n + 1) % 3 - 1);
                issue_pt(xh2, py0 + dy + oy0, pxbase + dx + ox0, nA0, nA1, ngya, ngxa, nsela);
                issue_pt(xh2, py1 + dy + oy1, pxbase + dx + ox1, nB0, nB1, ngyb, ngxb, nselb);
            }
            const u64* sd = (const u64*)&sdc[n * 8];
            u64 sd0 = sd[0], sd1 = sd[1], sd2 = sd[2], sd3 = sd[3];
            accp0 = combine_pt(A0, A1, gya, gxa, sela, sd0, sd1, sd2, sd3, accp0);
            accp1 = combine_pt(B0, B1, gyb, gxb, selb, sd0, sd1, sd2, sd3, accp1);
            if (n < 8) {
                A0 = nA0; A1 = nA1; B0 = nB0; B1 = nB1;
                gya = ngya; gxa = ngxa; sela = nsela;
                gyb = ngyb; gxb = ngxb; selb = nselb;
            }
        }

        int h = h0 + r0;
        float2 o0 = un2(accp0);
        float2 o1 = un2(accp1);
        out[((size_t)(b * 2 + 0) * H_ + h) * W_ + w] = o0.x;
        out[((size_t)(b * 2 + 1) * H_ + h) * W_ + w] = o0.y;
        out[((size_t)(b * 2 + 0) * H_ + h + 1) * W_ + w] = o1.x;
        out[((size_t)(b * 2 + 1) * H_ + h + 1) * W_ + w] = o1.y;
    }
}

// ---------------------------------------------------------------------------
extern "C" void kernel_launch(void* const* d_in, const int* in_sizes, int n_in,
                              void* d_out, int out_size) {
    const float* rgb = (const float*)d_in[0];
    const float* sar = (const float*)d_in[1];
    const float* wfm = (const float*)d_in[2];
    const float* wfs = (const float*)d_in[3];
    const float* wp  = (const float*)d_in[4];
    const float* bp  = (const float*)d_in[5];
    const float* wdc = (const float*)d_in[6];
    float* out = (float*)d_out;

    cudaFuncSetAttribute(kB_mat_fs_pack,
                         cudaFuncAttributeMaxDynamicSharedMemorySize, 196608);

    kAZ<<<512 + 33, 256>>>(rgb, wfm);
    kB_mat_fs_pack<<<dim3(H_ / KB_ROWS, B_), 256, 196608>>>(rgb, sar, wfs);
    kC_deform<<<dim3(H_ / TILE_H, B_), 128>>>(wp, bp, wdc, out);
}

// round 12
// speedup vs baseline: 1.1136x; 1.1064x over previous
#include <cuda_runtime.h>
#include <cuda_fp16.h>
#include <math.h>

#define B_  4
#define C_  2
#define H_  2048
#define W_  128
#define HP  2050
#define WP  130

typedef unsigned long long u64;

__device__ __forceinline__ u64 ffma2(u64 a, u64 b, u64 c) {
    u64 d; asm("fma.rn.f32x2 %0, %1, %2, %3;" : "=l"(d) : "l"(a), "l"(b), "l"(c)); return d;
}
__device__ __forceinline__ u64 dup2(float x) {
    u64 d; asm("mov.b64 %0, {%1, %1};" : "=l"(d) : "f"(x)); return d;
}
__device__ __forceinline__ u64 pk2(float x, float y) {
    u64 d; asm("mov.b64 %0, {%1, %2};" : "=l"(d) : "f"(x), "f"(y)); return d;
}
__device__ __forceinline__ float2 un2(u64 v) {
    float2 r; asm("mov.b64 {%0, %1}, %2;" : "=f"(r.x), "=f"(r.y) : "l"(v)); return r;
}
__device__ __forceinline__ __half2 h2dup(float x) {
    unsigned r; asm("cvt.rn.f16x2.f32 %0, %1, %1;" : "=r"(r) : "f"(x));
    return *(__half2*)&r;
}
__device__ __forceinline__ u64 cvlo(u64 p) {
    unsigned lo = (unsigned)p;
    float2 f = __half22float2(*(__half2*)&lo);
    return pk2(f.x, f.y);
}
__device__ __forceinline__ u64 cvhi(u64 p) {
    unsigned hi = (unsigned)(p >> 32);
    float2 f = __half22float2(*(__half2*)&hi);
    return pk2(f.x, f.y);
}

// Scratch
__device__ float      g_fm[B_ * C_ * 128 * 128];  // fm after sigmoid [b][c][k][w]
__device__ ulonglong2 g_xh2[B_ * HP * WP];        // x-duplicated fp16: slot x = (px[x], px[x+1])

// ---------------------------------------------------------------------------
// Kernel AZ: fused (avg+fm, r8 split-reduction form) and border-zero (fp16 only)
// blocks [0,512): kA; blocks [512,545): border zero
// ---------------------------------------------------------------------------
__global__ void kAZ(const float* __restrict__ rgb, const float* __restrict__ wfm) {
    if (blockIdx.x < 512) {
        __shared__ float red[128][2];
        int b = blockIdx.x >> 7;
        int i = blockIdx.x & 127;
        int j = threadIdx.x & 127;
        int half = threadIdx.x >> 7;

        const float* r0 = rgb + ((size_t)(b * 2 + 0) * H_ + i * 16 + half * 8) * W_ + j;
        const float* r1 = rgb + ((size_t)(b * 2 + 1) * H_ + i * 16 + half * 8) * W_ + j;
        float a0 = 0.f, a1 = 0.f;
#pragma unroll
        for (int r = 0; r < 8; r++) {
            a0 += __ldg(&r0[r * W_]);
            a1 += __ldg(&r1[r * W_]);
        }
        if (half == 1) { red[j][0] = a0; red[j][1] = a1; }
        __syncthreads();
        if (half == 0) {
            a0 = (a0 + red[j][0]) * (1.f / 16.f);
            a1 = (a1 + red[j][1]) * (1.f / 16.f);
            float w00 = __ldg(&wfm[0]), w01 = __ldg(&wfm[1]);
            float w10 = __ldg(&wfm[2]), w11 = __ldg(&wfm[3]);
            float z0 = w00 * a0 + w01 * a1;
            float z1 = w10 * a0 + w11 * a1;
            g_fm[((b * 2 + 0) * 128 + i) * 128 + j] = 1.f / (1.f + expf(-z0));
            g_fm[((b * 2 + 1) * 128 + i) * 128 + j] = 1.f / (1.f + expf(-z1));
        }
    } else {
        int tid = (blockIdx.x - 512) * 256 + threadIdx.x;
        if (tid >= B_ * HP) return;
        int b = tid / HP;
        int y = tid % HP;
        size_t rb = ((size_t)b * HP + y) * WP;
        u64* s = (u64*)(g_xh2 + rb);
        if (y == 0 || y == HP - 1) {
            for (int x = 0; x < WP; x++) {
                s[x * 2] = 0ULL; s[x * 2 + 1] = 0ULL;
            }
        } else {
            s[0] = 0ULL;                 // slot 0   .x  (px[0] = 0)
            s[(WP - 2) * 2 + 1] = 0ULL;  // slot 128 .y  (px[129] = 0)
            s[(WP - 1) * 2] = 0ULL;      // slot 129 .x
            s[(WP - 1) * 2 + 1] = 0ULL;  // slot 129 .y
        }
    }
}

// ---------------------------------------------------------------------------
// Kernel B: mat = rgb @ fm + rgb, fs mix, write ONLY the fp16 dup buffer.
// (r8 mainloop: 256 thr, thread tile 8 rows x 4 cols)
// ---------------------------------------------------------------------------
#define KB_ROWS 64
__global__ void __launch_bounds__(256, 1)
kB_mat_fs_pack(const float* __restrict__ rgb,
               const float* __restrict__ sar,
               const float* __restrict__ wfs) {
    extern __shared__ float sm[];
    float* s_fmi  = sm;            // [k][w][ch]
    float* s_rgbi = sm + 32768;    // [r][k][ch]

    int t = threadIdx.x;
    int lane = t & 31;
    int warp = t >> 5;
    int c0 = lane * 4;
    int r0 = warp * 8;
    int b  = blockIdx.y;
    int h0 = blockIdx.x * KB_ROWS;

    const float* fmb = g_fm + (size_t)b * 32768;
    for (int i = t; i < 16384; i += 256) {
        s_fmi[i * 2 + 0] = fmb[i];
        s_fmi[i * 2 + 1] = fmb[16384 + i];
    }
    const float* rgbb = rgb + (size_t)b * 2 * H_ * W_;
    for (int i = t; i < KB_ROWS * 128; i += 256) {
        int r = i >> 7, k = i & 127;
        s_rgbi[i * 2 + 0] = rgbb[(size_t)(h0 + r) * W_ + k];
        s_rgbi[i * 2 + 1] = rgbb[(size_t)H_ * W_ + (size_t)(h0 + r) * W_ + k];
    }
    __syncthreads();

    u64 acc[8][4];
#pragma unroll
    for (int r = 0; r < 8; r++)
#pragma unroll
        for (int c = 0; c < 4; c++) acc[r][c] = 0ULL;

#pragma unroll 2
    for (int k = 0; k < 128; k++) {
        const ulonglong2* fp = (const ulonglong2*)&s_fmi[(k * 128 + c0) * 2];
        ulonglong2 fA = fp[0], fB = fp[1];
#pragma unroll
        for (int r = 0; r < 8; r++) {
            u64 xv = *(const u64*)&s_rgbi[((r0 + r) * 128 + k) * 2];  // broadcast
            acc[r][0] = ffma2(xv, fA.x, acc[r][0]);
            acc[r][1] = ffma2(xv, fA.y, acc[r][1]);
            acc[r][2] = ffma2(xv, fB.x, acc[r][2]);
            acc[r][3] = ffma2(xv, fB.y, acc[r][3]);
        }
    }

    float wfs00 = __ldg(&wfs[0]), wfs01 = __ldg(&wfs[1]);
    float wfs10 = __ldg(&wfs[2]), wfs11 = __ldg(&wfs[3]);
    const float* sarb = sar + (size_t)b * 2 * H_ * W_;
    u64* hb = (u64*)(g_xh2 + (size_t)b * HP * WP);

#pragma unroll
    for (int r = 0; r < 8; r++) {
        int row = r0 + r;
        int h = h0 + row;
        float4 sA = *(const float4*)&sarb[(size_t)h * W_ + c0];
        float4 sB = *(const float4*)&sarb[(size_t)H_ * W_ + (size_t)h * W_ + c0];
        float sc0[4] = {sA.x, sA.y, sA.z, sA.w};
        float sc1[4] = {sB.x, sB.y, sB.z, sB.w};
#pragma unroll
        for (int c = 0; c < 4; c++) {
            float2 m = un2(acc[r][c]);
            float2 xf = un2(*(const u64*)&s_rgbi[(row * 128 + c0 + c) * 2]);
            float mat0 = m.x + xf.x;
            float mat1 = m.y + xf.y;
            float fs0 = wfs00 * mat0 + wfs01 * mat1;
            float fs1 = wfs10 * mat0 + wfs11 * mat1;
            int p = c0 + c + 1;
            size_t ridx = (size_t)(h + 1) * WP;
            __half2 ha = __floats2half2_rn(sc0[c], sc1[c]);
            __half2 hh = __floats2half2_rn(fs0, fs1);
            u64 hv = ((u64)(*(unsigned*)&hh) << 32) | (u64)(*(unsigned*)&ha);
            hb[(ridx + p) * 2] = hv;            // slot p   .x
            hb[(ridx + p - 1) * 2 + 1] = hv;    // slot p-1 .y
        }
    }
}

// ---------------------------------------------------------------------------
// Kernel C: software-pipelined offset conv (fp16 taps) + deform sampling.
// lb4 (measured-good). Tile loaded densely from the dup buffer.
// ---------------------------------------------------------------------------
__device__ __forceinline__ void comp_off(const ulonglong2 ip[4][3],
                                         const float* __restrict__ swq,
                                         const float* __restrict__ sbp, int n,
                                         float& offy0, float& offy1,
                                         float& offx0, float& offx1) {
    u64 ay0 = 0ULL, ay1 = 0ULL, ax0 = 0ULL, ax1 = 0ULL;
#pragma unroll
    for (int ky = 0; ky < 3; ky++) {
#pragma unroll
        for (int kx = 0; kx < 3; kx++) {
            int tap = ky * 3 + kx;
            ulonglong2 wy = *(const ulonglong2*)&swq[(n * 9 + tap) * 4];
            ulonglong2 wx = *(const ulonglong2*)&swq[((9 + n) * 9 + tap) * 4];
            ay0 = ffma2(ip[ky    ][kx].x, wy.x, ay0);
            ay0 = ffma2(ip[ky    ][kx].y, wy.y, ay0);
            ay1 = ffma2(ip[ky + 1][kx].x, wy.x, ay1);
            ay1 = ffma2(ip[ky + 1][kx].y, wy.y, ay1);
            ax0 = ffma2(ip[ky    ][kx].x, wx.x, ax0);
            ax0 = ffma2(ip[ky    ][kx].y, wx.y, ax0);
            ax1 = ffma2(ip[ky + 1][kx].x, wx.x, ax1);
            ax1 = ffma2(ip[ky + 1][kx].y, wx.y, ax1);
        }
    }
    float2 t;
    t = un2(ay0); offy0 = t.x + t.y + sbp[n];
    t = un2(ay1); offy1 = t.x + t.y + sbp[n];
    t = un2(ax0); offx0 = t.x + t.y + sbp[9 + n];
    t = un2(ax1); offx1 = t.x + t.y + sbp[9 + n];
}

__device__ __forceinline__ void issue_pt(const ulonglong2* __restrict__ xh2,
                                         float py, float px,
                                         ulonglong2& U0, ulonglong2& U1,
                                         float& gy, float& gx, bool& sel) {
    float fy = floorf(py), fx = floorf(px);
    gy = py - fy; gx = px - fx;   // exact: clamped corners read zero pad pixels
    int y0 = (int)fminf(fmaxf(fy,       0.f), (float)(HP - 1));
    int y1 = (int)fminf(fmaxf(fy + 1.f, 0.f), (float)(HP - 1));
    int x0 = (int)fminf(fmaxf(fx,       0.f), (float)(WP - 1));
    int x1 = (int)fminf(fmaxf(fx + 1.f, 0.f), (float)(WP - 1));
    sel = (x1 != x0);
    U0 = __ldg(&xh2[y0 * WP + x0]);
    U1 = __ldg(&xh2[y1 * WP + x0]);
}

__device__ __forceinline__ u64 combine_pt(ulonglong2 U0, ulonglong2 U1,
                                          float gy, float gx, bool sel,
                                          u64 sd0, u64 sd1, u64 sd2, u64 sd3, u64 acc) {
    unsigned p00l = (unsigned)U0.x, p00h = (unsigned)(U0.x >> 32);
    unsigned q01l = (unsigned)U0.y, q01h = (unsigned)(U0.y >> 32);
    unsigned p10l = (unsigned)U1.x, p10h = (unsigned)(U1.x >> 32);
    unsigned q11l = (unsigned)U1.y, q11h = (unsigned)(U1.y >> 32);
    unsigned p01l = sel ? q01l : p00l, p01h = sel ? q01h : p00h;
    unsigned p11l = sel ? q11l : p10l, p11h = sel ? q11h : p10h;

    __half2 hgx = h2dup(gx), hhx = h2dup(1.f - gx);

    __half2 cy0l = __hfma2(hgx, *(__half2*)&p01l, __hmul2(hhx, *(__half2*)&p00l));
    __half2 cy0h = __hfma2(hgx, *(__half2*)&p01h, __hmul2(hhx, *(__half2*)&p00h));
    __half2 cy1l = __hfma2(hgx, *(__half2*)&p11l, __hmul2(hhx, *(__half2*)&p10l));
    __half2 cy1h = __hfma2(hgx, *(__half2*)&p11h, __hmul2(hhx, *(__half2*)&p10h));

    float2 f0l = __half22float2(cy0l), f0h = __half22float2(cy0h);
    float2 f1l = __half22float2(cy1l), f1h = __half22float2(cy1h);

    u64 wy1d = dup2(gy), wy0d = dup2(1.f - gy);
    u64 c01 = ffma2(wy1d, pk2(f1l.x, f1l.y), ffma2(wy0d, pk2(f0l.x, f0l.y), 0ULL));
    u64 c23 = ffma2(wy1d, pk2(f1h.x, f1h.y), ffma2(wy0d, pk2(f0h.x, f0h.y), 0ULL));

    float2 v01 = un2(c01), v23 = un2(c23);
    acc = ffma2(dup2(v01.x), sd0, acc);
    acc = ffma2(dup2(v01.y), sd1, acc);
    acc = ffma2(dup2(v23.x), sd2, acc);
    acc = ffma2(dup2(v23.y), sd3, acc);
    return acc;
}

#define TILE_H 8
__global__ void __launch_bounds__(128, 4)
kC_deform(const float* __restrict__ wp,
          const float* __restrict__ bp,
          const float* __restrict__ wdc,
          float* __restrict__ out) {
    __shared__ __align__(16) u64   srow[TILE_H + 2][WP];  // fp16x4 per pixel
    __shared__ __align__(16) float swq[648];   // [j][tap][c]
    __shared__ __align__(16) float sdc[72];    // [n][c][(o0,o1)]
    __shared__ float sbp[18];

    int w  = threadIdx.x;
    int h0 = blockIdx.x * TILE_H;
    int b  = blockIdx.y;

    const ulonglong2* xh2 = g_xh2 + (size_t)b * HP * WP;

    // dense tile fill: dup slot 2i holds pixels (2i, 2i+1)
    for (int i = threadIdx.x; i < (TILE_H + 2) * 65; i += 128) {
        int ry = i / 65, rx2 = i % 65;
        ulonglong2 U = __ldg(&xh2[(size_t)(h0 + ry) * WP + rx2 * 2]);
        *(ulonglong2*)&srow[ry][rx2 * 2] = U;
    }
    for (int i = threadIdx.x; i < 648; i += 128) {
        int j = i / 36, rem = i % 36, tap = rem / 4, c = rem % 4;
        swq[i] = wp[j * 36 + c * 9 + tap];
    }
    if (threadIdx.x < 72) {
        int i = threadIdx.x;
        int n = i / 8, rc = i % 8, c = rc / 2, o = rc % 2;
        sdc[i] = wdc[o * 36 + c * 9 + n];
    }
    if (threadIdx.x < 18) sbp[threadIdx.x] = bp[threadIdx.x];
    __syncthreads();

    const float pxbase = (float)(w + 1);

#pragma unroll 1
    for (int rp = 0; rp < TILE_H / 2; rp++) {
        int r0 = rp * 2;
        ulonglong2 ip[4][3];
#pragma unroll
        for (int ry = 0; ry < 4; ry++)
#pragma unroll
            for (int kx = 0; kx < 3; kx++) {
                u64 hsh = srow[r0 + ry][w + kx];
                ip[ry][kx].x = cvlo(hsh);
                ip[ry][kx].y = cvhi(hsh);
            }

        u64 accp0 = 0ULL, accp1 = 0ULL;
        float py0 = (float)(h0 + r0 + 1);
        float py1 = (float)(h0 + r0 + 2);

        ulonglong2 A0, A1, B0, B1;
        float gya, gxa, gyb, gxb;
        bool sela, selb;
        {
            float oy0, oy1, ox0, ox1;
            comp_off(ip, swq, sbp, 0, oy0, oy1, ox0, ox1);
            issue_pt(xh2, py0 - 1.f + oy0, pxbase - 1.f + ox0, A0, A1, gya, gxa, sela);
            issue_pt(xh2, py1 - 1.f + oy1, pxbase - 1.f + ox1, B0, B1, gyb, gxb, selb);
        }

#pragma unroll
        for (int n = 0; n < 9; n++) {
            ulonglong2 nA0, nA1, nB0, nB1;
            float ngya, ngxa, ngyb, ngxb;
            bool nsela = false, nselb = false;
            if (n < 8) {
                float oy0, oy1, ox0, ox1;
                comp_off(ip, swq, sbp, n + 1, oy0, oy1, ox0, ox1);
                float dy = (float)((n + 1) / 3 - 1);
                float dx = (float)((n + 1) % 3 - 1);
                issue_pt(xh2, py0 + dy + oy0, pxbase + dx + ox0, nA0, nA1, ngya, ngxa, nsela);
                issue_pt(xh2, py1 + dy + oy1, pxbase + dx + ox1, nB0, nB1, ngyb, ngxb, nselb);
            }
            const u64* sd = (const u64*)&sdc[n * 8];
            u64 sd0 = sd[0], sd1 = sd[1], sd2 = sd[2], sd3 = sd[3];
            accp0 = combine_pt(A0, A1, gya, gxa, sela, sd0, sd1, sd2, sd3, accp0);
            accp1 = combine_pt(B0, B1, gyb, gxb, selb, sd0, sd1, sd2, sd3, accp1);
            if (n < 8) {
                A0 = nA0; A1 = nA1; B0 = nB0; B1 = nB1;
                gya = ngya; gxa = ngxa; sela = nsela;
                gyb = ngyb; gxb = ngxb; selb = nselb;
            }
        }

        int h = h0 + r0;
        float2 o0 = un2(accp0);
        float2 o1 = un2(accp1);
        out[((size_t)(b * 2 + 0) * H_ + h) * W_ + w] = o0.x;
        out[((size_t)(b * 2 + 1) * H_ + h) * W_ + w] = o0.y;
        out[((size_t)(b * 2 + 0) * H_ + h + 1) * W_ + w] = o1.x;
        out[((size_t)(b * 2 + 1) * H_ + h + 1) * W_ + w] = o1.y;
    }
}

// ---------------------------------------------------------------------------
extern "C" void kernel_launch(void* const* d_in, const int* in_sizes, int n_in,
                              void* d_out, int out_size) {
    const float* rgb = (const float*)d_in[0];
    const float* sar = (const float*)d_in[1];
    const float* wfm = (const float*)d_in[2];
    const float* wfs = (const float*)d_in[3];
    const float* wp  = (const float*)d_in[4];
    const float* bp  = (const float*)d_in[5];
    const float* wdc = (const float*)d_in[6];
    float* out = (float*)d_out;

    cudaFuncSetAttribute(kB_mat_fs_pack,
                         cudaFuncAttributeMaxDynamicSharedMemorySize, 196608);

    kAZ<<<512 + 33, 256>>>(rgb, wfm);
    kB_mat_fs_pack<<<dim3(H_ / KB_ROWS, B_), 256, 196608>>>(rgb, sar, wfs);
    kC_deform<<<dim3(H_ / TILE_H, B_), 128>>>(wp, bp, wdc, out);
}

// round 13
// speedup vs baseline: 1.1154x; 1.0017x over previous
#include <cuda_runtime.h>
#include <cuda_fp16.h>
#include <math.h>

#define B_  4
#define C_  2
#define H_  2048
#define W_  128
#define HP  2050
#define WP  130

typedef unsigned long long u64;

__device__ __forceinline__ u64 ffma2(u64 a, u64 b, u64 c) {
    u64 d; asm("fma.rn.f32x2 %0, %1, %2, %3;" : "=l"(d) : "l"(a), "l"(b), "l"(c)); return d;
}
__device__ __forceinline__ u64 dup2(float x) {
    u64 d; asm("mov.b64 %0, {%1, %1};" : "=l"(d) : "f"(x)); return d;
}
__device__ __forceinline__ u64 pk2(float x, float y) {
    u64 d; asm("mov.b64 %0, {%1, %2};" : "=l"(d) : "f"(x), "f"(y)); return d;
}
__device__ __forceinline__ float2 un2(u64 v) {
    float2 r; asm("mov.b64 {%0, %1}, %2;" : "=f"(r.x), "=f"(r.y) : "l"(v)); return r;
}
__device__ __forceinline__ __half2 h2dup(float x) {
    unsigned r; asm("cvt.rn.f16x2.f32 %0, %1, %1;" : "=r"(r) : "f"(x));
    return *(__half2*)&r;
}
__device__ __forceinline__ u64 cvlo(u64 p) {
    unsigned lo = (unsigned)p;
    float2 f = __half22float2(*(__half2*)&lo);
    return pk2(f.x, f.y);
}
__device__ __forceinline__ u64 cvhi(u64 p) {
    unsigned hi = (unsigned)(p >> 32);
    float2 f = __half22float2(*(__half2*)&hi);
    return pk2(f.x, f.y);
}

// Scratch
__device__ float      g_fm[B_ * C_ * 128 * 128];  // fm after sigmoid [b][c][k][w]
__device__ ulonglong2 g_xh2[B_ * HP * WP];        // x-duplicated fp16: slot x = (px[x], px[x+1])

// ---------------------------------------------------------------------------
// Kernel AZ: fused (avg+fm, r8 split-reduction form) and border-zero (fp16 only)
// blocks [0,512): kA; blocks [512,545): border zero
// ---------------------------------------------------------------------------
__global__ void kAZ(const float* __restrict__ rgb, const float* __restrict__ wfm) {
    if (blockIdx.x < 512) {
        __shared__ float red[128][2];
        int b = blockIdx.x >> 7;
        int i = blockIdx.x & 127;
        int j = threadIdx.x & 127;
        int half = threadIdx.x >> 7;

        const float* r0 = rgb + ((size_t)(b * 2 + 0) * H_ + i * 16 + half * 8) * W_ + j;
        const float* r1 = rgb + ((size_t)(b * 2 + 1) * H_ + i * 16 + half * 8) * W_ + j;
        float a0 = 0.f, a1 = 0.f;
#pragma unroll
        for (int r = 0; r < 8; r++) {
            a0 += __ldg(&r0[r * W_]);
            a1 += __ldg(&r1[r * W_]);
        }
        if (half == 1) { red[j][0] = a0; red[j][1] = a1; }
        __syncthreads();
        if (half == 0) {
            a0 = (a0 + red[j][0]) * (1.f / 16.f);
            a1 = (a1 + red[j][1]) * (1.f / 16.f);
            float w00 = __ldg(&wfm[0]), w01 = __ldg(&wfm[1]);
            float w10 = __ldg(&wfm[2]), w11 = __ldg(&wfm[3]);
            float z0 = w00 * a0 + w01 * a1;
            float z1 = w10 * a0 + w11 * a1;
            g_fm[((b * 2 + 0) * 128 + i) * 128 + j] = 1.f / (1.f + expf(-z0));
            g_fm[((b * 2 + 1) * 128 + i) * 128 + j] = 1.f / (1.f + expf(-z1));
        }
    } else {
        int tid = (blockIdx.x - 512) * 256 + threadIdx.x;
        if (tid >= B_ * HP) return;
        int b = tid / HP;
        int y = tid % HP;
        size_t rb = ((size_t)b * HP + y) * WP;
        u64* s = (u64*)(g_xh2 + rb);
        if (y == 0 || y == HP - 1) {
            for (int x = 0; x < WP; x++) {
                s[x * 2] = 0ULL; s[x * 2 + 1] = 0ULL;
            }
        } else {
            s[0] = 0ULL;                 // slot 0   .x  (px[0] = 0)
            s[(WP - 2) * 2 + 1] = 0ULL;  // slot 128 .y  (px[129] = 0)
            s[(WP - 1) * 2] = 0ULL;      // slot 129 .x
            s[(WP - 1) * 2 + 1] = 0ULL;  // slot 129 .y
        }
    }
}

// ---------------------------------------------------------------------------
// Kernel B: mat = rgb @ fm + rgb, fs mix, write ONLY the fp16 dup buffer.
// (r8 mainloop: 256 thr, thread tile 8 rows x 4 cols)
// ---------------------------------------------------------------------------
#define KB_ROWS 64
__global__ void __launch_bounds__(256, 1)
kB_mat_fs_pack(const float* __restrict__ rgb,
               const float* __restrict__ sar,
               const float* __restrict__ wfs) {
    extern __shared__ float sm[];
    float* s_fmi  = sm;            // [k][w][ch]
    float* s_rgbi = sm + 32768;    // [r][k][ch]

    int t = threadIdx.x;
    int lane = t & 31;
    int warp = t >> 5;
    int c0 = lane * 4;
    int r0 = warp * 8;
    int b  = blockIdx.y;
    int h0 = blockIdx.x * KB_ROWS;

    const float* fmb = g_fm + (size_t)b * 32768;
    for (int i = t; i < 16384; i += 256) {
        s_fmi[i * 2 + 0] = fmb[i];
        s_fmi[i * 2 + 1] = fmb[16384 + i];
    }
    const float* rgbb = rgb + (size_t)b * 2 * H_ * W_;
    for (int i = t; i < KB_ROWS * 128; i += 256) {
        int r = i >> 7, k = i & 127;
        s_rgbi[i * 2 + 0] = rgbb[(size_t)(h0 + r) * W_ + k];
        s_rgbi[i * 2 + 1] = rgbb[(size_t)H_ * W_ + (size_t)(h0 + r) * W_ + k];
    }
    __syncthreads();

    u64 acc[8][4];
#pragma unroll
    for (int r = 0; r < 8; r++)
#pragma unroll
        for (int c = 0; c < 4; c++) acc[r][c] = 0ULL;

#pragma unroll 2
    for (int k = 0; k < 128; k++) {
        const ulonglong2* fp = (const ulonglong2*)&s_fmi[(k * 128 + c0) * 2];
        ulonglong2 fA = fp[0], fB = fp[1];
#pragma unroll
        for (int r = 0; r < 8; r++) {
            u64 xv = *(const u64*)&s_rgbi[((r0 + r) * 128 + k) * 2];  // broadcast
            acc[r][0] = ffma2(xv, fA.x, acc[r][0]);
            acc[r][1] = ffma2(xv, fA.y, acc[r][1]);
            acc[r][2] = ffma2(xv, fB.x, acc[r][2]);
            acc[r][3] = ffma2(xv, fB.y, acc[r][3]);
        }
    }

    float wfs00 = __ldg(&wfs[0]), wfs01 = __ldg(&wfs[1]);
    float wfs10 = __ldg(&wfs[2]), wfs11 = __ldg(&wfs[3]);
    const float* sarb = sar + (size_t)b * 2 * H_ * W_;
    u64* hb = (u64*)(g_xh2 + (size_t)b * HP * WP);

#pragma unroll
    for (int r = 0; r < 8; r++) {
        int row = r0 + r;
        int h = h0 + row;
        float4 sA = *(const float4*)&sarb[(size_t)h * W_ + c0];
        float4 sB = *(const float4*)&sarb[(size_t)H_ * W_ + (size_t)h * W_ + c0];
        float sc0[4] = {sA.x, sA.y, sA.z, sA.w};
        float sc1[4] = {sB.x, sB.y, sB.z, sB.w};
#pragma unroll
        for (int c = 0; c < 4; c++) {
            float2 m = un2(acc[r][c]);
            float2 xf = un2(*(const u64*)&s_rgbi[(row * 128 + c0 + c) * 2]);
            float mat0 = m.x + xf.x;
            float mat1 = m.y + xf.y;
            float fs0 = wfs00 * mat0 + wfs01 * mat1;
            float fs1 = wfs10 * mat0 + wfs11 * mat1;
            int p = c0 + c + 1;
            size_t ridx = (size_t)(h + 1) * WP;
            __half2 ha = __floats2half2_rn(sc0[c], sc1[c]);
            __half2 hh = __floats2half2_rn(fs0, fs1);
            u64 hv = ((u64)(*(unsigned*)&hh) << 32) | (u64)(*(unsigned*)&ha);
            hb[(ridx + p) * 2] = hv;            // slot p   .x
            hb[(ridx + p - 1) * 2 + 1] = hv;    // slot p-1 .y
        }
    }
}

// ---------------------------------------------------------------------------
// Kernel C: software-pipelined offset conv (fp16 taps) + deform sampling.
// lb4 (measured-good). Tile loaded densely from the dup buffer.
// ---------------------------------------------------------------------------
__device__ __forceinline__ void comp_off(const ulonglong2 ip[4][3],
                                         const float* __restrict__ swq,
                                         const float* __restrict__ sbp, int n,
                                         float& offy0, float& offy1,
                                         float& offx0, float& offx1) {
    u64 ay0 = 0ULL, ay1 = 0ULL, ax0 = 0ULL, ax1 = 0ULL;
#pragma unroll
    for (int ky = 0; ky < 3; ky++) {
#pragma unroll
        for (int kx = 0; kx < 3; kx++) {
            int tap = ky * 3 + kx;
            ulonglong2 wy = *(const ulonglong2*)&swq[(n * 9 + tap) * 4];
            ulonglong2 wx = *(const ulonglong2*)&swq[((9 + n) * 9 + tap) * 4];
            ay0 = ffma2(ip[ky    ][kx].x, wy.x, ay0);
            ay0 = ffma2(ip[ky    ][kx].y, wy.y, ay0);
            ay1 = ffma2(ip[ky + 1][kx].x, wy.x, ay1);
            ay1 = ffma2(ip[ky + 1][kx].y, wy.y, ay1);
            ax0 = ffma2(ip[ky    ][kx].x, wx.x, ax0);
            ax0 = ffma2(ip[ky    ][kx].y, wx.y, ax0);
            ax1 = ffma2(ip[ky + 1][kx].x, wx.x, ax1);
            ax1 = ffma2(ip[ky + 1][kx].y, wx.y, ax1);
        }
    }
    float2 t;
    t = un2(ay0); offy0 = t.x + t.y + sbp[n];
    t = un2(ay1); offy1 = t.x + t.y + sbp[n];
    t = un2(ax0); offx0 = t.x + t.y + sbp[9 + n];
    t = un2(ax1); offx1 = t.x + t.y + sbp[9 + n];
}

__device__ __forceinline__ void issue_pt(const ulonglong2* __restrict__ xh2,
                                         float py, float px,
                                         ulonglong2& U0, ulonglong2& U1,
                                         float& gy, float& gx, bool& sel) {
    float fy = floorf(py), fx = floorf(px);
    gy = py - fy; gx = px - fx;   // exact: clamped corners read zero pad pixels
    int y0 = (int)fminf(fmaxf(fy,       0.f), (float)(HP - 1));
    int y1 = (int)fminf(fmaxf(fy + 1.f, 0.f), (float)(HP - 1));
    int x0 = (int)fminf(fmaxf(fx,       0.f), (float)(WP - 1));
    int x1 = (int)fminf(fmaxf(fx + 1.f, 0.f), (float)(WP - 1));
    sel = (x1 != x0);
    U0 = __ldg(&xh2[y0 * WP + x0]);
    U1 = __ldg(&xh2[y1 * WP + x0]);
}

__device__ __forceinline__ u64 combine_pt(ulonglong2 U0, ulonglong2 U1,
                                          float gy, float gx, bool sel,
                                          u64 sd0, u64 sd1, u64 sd2, u64 sd3, u64 acc) {
    unsigned p00l = (unsigned)U0.x, p00h = (unsigned)(U0.x >> 32);
    unsigned q01l = (unsigned)U0.y, q01h = (unsigned)(U0.y >> 32);
    unsigned p10l = (unsigned)U1.x, p10h = (unsigned)(U1.x >> 32);
    unsigned q11l = (unsigned)U1.y, q11h = (unsigned)(U1.y >> 32);
    unsigned p01l = sel ? q01l : p00l, p01h = sel ? q01h : p00h;
    unsigned p11l = sel ? q11l : p10l, p11h = sel ? q11h : p10h;

    __half2 hgx = h2dup(gx), hhx = h2dup(1.f - gx);

    __half2 cy0l = __hfma2(hgx, *(__half2*)&p01l, __hmul2(hhx, *(__half2*)&p00l));
    __half2 cy0h = __hfma2(hgx, *(__half2*)&p01h, __hmul2(hhx, *(__half2*)&p00h));
    __half2 cy1l = __hfma2(hgx, *(__half2*)&p11l, __hmul2(hhx, *(__half2*)&p10l));
    __half2 cy1h = __hfma2(hgx, *(__half2*)&p11h, __hmul2(hhx, *(__half2*)&p10h));

    float2 f0l = __half22float2(cy0l), f0h = __half22float2(cy0h);
    float2 f1l = __half22float2(cy1l), f1h = __half22float2(cy1h);

    u64 wy1d = dup2(gy), wy0d = dup2(1.f - gy);
    u64 c01 = ffma2(wy1d, pk2(f1l.x, f1l.y), ffma2(wy0d, pk2(f0l.x, f0l.y), 0ULL));
    u64 c23 = ffma2(wy1d, pk2(f1h.x, f1h.y), ffma2(wy0d, pk2(f0h.x, f0h.y), 0ULL));

    float2 v01 = un2(c01), v23 = un2(c23);
    acc = ffma2(dup2(v01.x), sd0, acc);
    acc = ffma2(dup2(v01.y), sd1, acc);
    acc = ffma2(dup2(v23.x), sd2, acc);
    acc = ffma2(dup2(v23.y), sd3, acc);
    return acc;
}

#define TILE_H 8
__global__ void __launch_bounds__(128, 4)
kC_deform(const float* __restrict__ wp,
          const float* __restrict__ bp,
          const float* __restrict__ wdc,
          float* __restrict__ out) {
    __shared__ __align__(16) u64   srow[TILE_H + 2][WP];  // fp16x4 per pixel
    __shared__ __align__(16) float swq[648];   // [j][tap][c]
    __shared__ __align__(16) float sdc[72];    // [n][c][(o0,o1)]
    __shared__ float sbp[18];

    int w  = threadIdx.x;
    int h0 = blockIdx.x * TILE_H;
    int b  = blockIdx.y;

    const ulonglong2* xh2 = g_xh2 + (size_t)b * HP * WP;

    // dense tile fill: dup slot 2i holds pixels (2i, 2i+1)
    for (int i = threadIdx.x; i < (TILE_H + 2) * 65; i += 128) {
        int ry = i / 65, rx2 = i % 65;
        ulonglong2 U = __ldg(&xh2[(size_t)(h0 + ry) * WP + rx2 * 2]);
        *(ulonglong2*)&srow[ry][rx2 * 2] = U;
    }
    for (int i = threadIdx.x; i < 648; i += 128) {
        int j = i / 36, rem = i % 36, tap = rem / 4, c = rem % 4;
        swq[i] = wp[j * 36 + c * 9 + tap];
    }
    if (threadIdx.x < 72) {
        int i = threadIdx.x;
        int n = i / 8, rc = i % 8, c = rc / 2, o = rc % 2;
        sdc[i] = wdc[o * 36 + c * 9 + n];
    }
    if (threadIdx.x < 18) sbp[threadIdx.x] = bp[threadIdx.x];
    __syncthreads();

    const float pxbase = (float)(w + 1);

#pragma unroll 1
    for (int rp = 0; rp < TILE_H / 2; rp++) {
        int r0 = rp * 2;
        ulonglong2 ip[4][3];
#pragma unroll
        for (int ry = 0; ry < 4; ry++)
#pragma unroll
            for (int kx = 0; kx < 3; kx++) {
                u64 hsh = srow[r0 + ry][w + kx];
                ip[ry][kx].x = cvlo(hsh);
                ip[ry][kx].y = cvhi(hsh);
            }

        u64 accp0 = 0ULL, accp1 = 0ULL;
        float py0 = (float)(h0 + r0 + 1);
        float py1 = (float)(h0 + r0 + 2);

        ulonglong2 A0, A1, B0, B1;
        float gya, gxa, gyb, gxb;
        bool sela, selb;
        {
            float oy0, oy1, ox0, ox1;
            comp_off(ip, swq, sbp, 0, oy0, oy1, ox0, ox1);
            issue_pt(xh2, py0 - 1.f + oy0, pxbase - 1.f + ox0, A0, A1, gya, gxa, sela);
            issue_pt(xh2, py1 - 1.f + oy1, pxbase - 1.f + ox1, B0, B1, gyb, gxb, selb);
        }

#pragma unroll
        for (int n = 0; n < 9; n++) {
            ulonglong2 nA0, nA1, nB0, nB1;
            float ngya, ngxa, ngyb, ngxb;
            bool nsela = false, nselb = false;
            if (n < 8) {
                float oy0, oy1, ox0, ox1;
                comp_off(ip, swq, sbp, n + 1, oy0, oy1, ox0, ox1);
                float dy = (float)((n + 1) / 3 - 1);
                float dx = (float)((n + 1) % 3 - 1);
                issue_pt(xh2, py0 + dy + oy0, pxbase + dx + ox0, nA0, nA1, ngya, ngxa, nsela);
                issue_pt(xh2, py1 + dy + oy1, pxbase + dx + ox1, nB0, nB1, ngyb, ngxb, nselb);
            }
            const u64* sd = (const u64*)&sdc[n * 8];
            u64 sd0 = sd[0], sd1 = sd[1], sd2 = sd[2], sd3 = sd[3];
            accp0 = combine_pt(A0, A1, gya, gxa, sela, sd0, sd1, sd2, sd3, accp0);
            accp1 = combine_pt(B0, B1, gyb, gxb, selb, sd0, sd1, sd2, sd3, accp1);
            if (n < 8) {
                A0 = nA0; A1 = nA1; B0 = nB0; B1 = nB1;
                gya = ngya; gxa = ngxa; sela = nsela;
                gyb = ngyb; gxb = ngxb; selb = nselb;
            }
        }

        int h = h0 + r0;
        float2 o0 = un2(accp0);
        float2 o1 = un2(accp1);
        out[((size_t)(b * 2 + 0) * H_ + h) * W_ + w] = o0.x;
        out[((size_t)(b * 2 + 1) * H_ + h) * W_ + w] = o0.y;
        out[((size_t)(b * 2 + 0) * H_ + h + 1) * W_ + w] = o1.x;
        out[((size_t)(b * 2 + 1) * H_ + h + 1) * W_ + w] = o1.y;
    }
}

// ---------------------------------------------------------------------------
extern "C" void kernel_launch(void* const* d_in, const int* in_sizes, int n_in,
                              void* d_out, int out_size) {
    const float* rgb = (const float*)d_in[0];
    const float* sar = (const float*)d_in[1];
    const float* wfm = (const float*)d_in[2];
    const float* wfs = (const float*)d_in[3];
    const float* wp  = (const float*)d_in[4];
    const float* bp  = (const float*)d_in[5];
    const float* wdc = (const float*)d_in[6];
    float* out = (float*)d_out;

    cudaFuncSetAttribute(kB_mat_fs_pack,
                         cudaFuncAttributeMaxDynamicSharedMemorySize, 196608);

    kAZ<<<512 + 33, 256>>>(rgb, wfm);
    kB_mat_fs_pack<<<dim3(H_ / KB_ROWS, B_), 256, 196608>>>(rgb, sar, wfs);
    kC_deform<<<dim3(H_ / TILE_H, B_), 128>>>(wp, bp, wdc, out);
}